// round 17
// baseline (speedup 1.0000x reference)
#include <cuda_runtime.h>
#include <cuda_bf16.h>
#include <math.h>
#include <stdint.h>

// ---------------------------------------------------------------------------
// Problem constants
// ---------------------------------------------------------------------------
static constexpr int NN = 50000;    // nodes
static constexpr int NE = 800000;   // edges
static constexpr int F1 = 128;      // in_feats
static constexpr int HF = 256;      // h_feats
static constexpr int CF = 32;       // classes

// ---------------------------------------------------------------------------
// Scratch (device globals -- no allocation allowed)
// ---------------------------------------------------------------------------
__device__ __align__(16) __nv_bfloat16 g_p1h[(size_t)NE * HF];
__device__ __align__(16) __nv_bfloat16 g_p1l[(size_t)NE * HF];
__device__ __align__(16) __nv_bfloat16 g_p2h[(size_t)NE * HF];
__device__ __align__(16) __nv_bfloat16 g_p2l[(size_t)NE * HF];
__device__ __align__(16) __nv_bfloat16 g_rwh[(size_t)NE * F1];
__device__ __align__(16) __nv_bfloat16 g_rwl[(size_t)NE * F1];

__device__ __align__(16) float g_h1 [(size_t)NN * HF];
__device__ __align__(16) float g_hN [(size_t)NN * HF];
__device__ float g_cos[NE];
__device__ int   g_deg[NN];

// split-bf16 weights, pre-transposed to [N, K] K-major
static constexpr size_t WT_TOTAL = 278528;
__device__ __align__(16) __nv_bfloat16 g_bwh[WT_TOTAL];
__device__ __align__(16) __nv_bfloat16 g_bwl[WT_TOTAL];

// ---------------------------------------------------------------------------
// helpers
// ---------------------------------------------------------------------------
__device__ __forceinline__ uint32_t smem_u32(const void* p) {
    uint32_t a;
    asm("{ .reg .u64 t; cvta.to.shared.u64 t, %1; cvt.u32.u64 %0, t; }" : "=r"(a) : "l"(p));
    return a;
}

__device__ __forceinline__ void ldm4(uint32_t& r0, uint32_t& r1, uint32_t& r2, uint32_t& r3,
                                     uint32_t addr) {
    asm volatile("ldmatrix.sync.aligned.m8n8.x4.shared.b16 {%0,%1,%2,%3}, [%4];"
                 : "=r"(r0), "=r"(r1), "=r"(r2), "=r"(r3) : "r"(addr));
}

__device__ __forceinline__ void mma16816(float* c, const uint32_t* a, const uint32_t* b) {
    asm volatile("mma.sync.aligned.m16n8k16.row.col.f32.bf16.bf16.f32 "
                 "{%0,%1,%2,%3}, {%4,%5,%6,%7}, {%8,%9}, {%0,%1,%2,%3};"
                 : "+f"(c[0]), "+f"(c[1]), "+f"(c[2]), "+f"(c[3])
                 : "r"(a[0]), "r"(a[1]), "r"(a[2]), "r"(a[3]), "r"(b[0]), "r"(b[1]));
}

// split one fp32 pair into packed bf16 hi + bf16 lo
__device__ __forceinline__ uint32_t split2(float a, float b, uint32_t& lo) {
    __nv_bfloat16 ha = __float2bfloat16(a), hb = __float2bfloat16(b);
    float ra = a - __bfloat162float(ha);
    float rb = b - __bfloat162float(hb);
    __nv_bfloat16 la = __float2bfloat16(ra), lb = __float2bfloat16(rb);
    lo = (uint32_t)__bfloat16_as_ushort(la) | ((uint32_t)__bfloat16_as_ushort(lb) << 16);
    return (uint32_t)__bfloat16_as_ushort(ha) | ((uint32_t)__bfloat16_as_ushort(hb) << 16);
}

// pack float2 -> bf16x2 (x low, y high)
__device__ __forceinline__ uint32_t pack_bf16x2(float x, float y) {
    uint32_t r;
    asm("cvt.rn.bf16x2.f32 %0, %1, %2;" : "=r"(r) : "f"(y), "f"(x));
    return r;
}

static constexpr int RS = 144;           // SMEM row stride bytes (64 bf16 + pad)
static constexpr int AT = 128 * RS;      // one A part (hi or lo): 18432

// ---------------------------------------------------------------------------
// zero kernel (counted launch; also used so ncu -s 5 lands on gemm_chain)
// ---------------------------------------------------------------------------
__global__ void zero_kernel(float4* __restrict__ p, int n4)
{
    const int i = blockIdx.x * 256 + threadIdx.x;
    if (i < n4) p[i] = make_float4(0.f, 0.f, 0.f, 0.f);
}

// ---------------------------------------------------------------------------
// Weight pre-transform: W[K,N] fp32 -> Bt_hi/Bt_lo [N,K] bf16
// ---------------------------------------------------------------------------
__global__ void conv_w_kernel(const float* __restrict__ W, int K, int N,
                              __nv_bfloat16* __restrict__ hi, __nv_bfloat16* __restrict__ lo)
{
    const int idx = blockIdx.x * 256 + threadIdx.x;
    if (idx >= K * N) return;
    const int k = idx / N;
    const int n = idx - k * N;
    const float x = W[idx];
    const __nv_bfloat16 h = __float2bfloat16(x);
    const float r = x - __bfloat162float(h);
    hi[(size_t)n * K + k] = h;
    lo[(size_t)n * K + k] = __float2bfloat16(r);
}

// ---------------------------------------------------------------------------
// bf16 split-3 GEMM (A pre-split bf16 hi/lo, cp.async double-buffered).
// Epilogue: bias (+relu) (+msg) then scatter / split-store / fp32 store.
// ---------------------------------------------------------------------------
template<int CTA_N, bool RELU_OUT, bool MSG_OUT, bool SCATTER_OUT, bool OUT_SPLIT>
__launch_bounds__(256, 2)
__global__ void gemm_mma(const __nv_bfloat16* __restrict__ Ah,
                         const __nv_bfloat16* __restrict__ Al,
                         const __nv_bfloat16* __restrict__ Bh,
                         const __nv_bfloat16* __restrict__ Bl,
                         const float* __restrict__ bias,
                         float* __restrict__ C,
                         __nv_bfloat16* __restrict__ Ch,
                         __nv_bfloat16* __restrict__ Cl,
                         int M, int K, int N,
                         const float* __restrict__ cosv,
                         const float* __restrict__ hfeat,
                         const int* __restrict__ src,
                         const int* __restrict__ dst)
{
    extern __shared__ char sm[];
    constexpr int S_B  = 4 * AT;
    constexpr int SPAN = CTA_N / 2;
    constexpr int NI   = SPAN / 8;

    const int tid    = threadIdx.x;
    const int lane   = tid & 31;
    const int warp   = tid >> 5;
    const int warp_m = warp & 3;
    const int warp_n = warp >> 2;
    const int m0     = blockIdx.x * 128;
    const int n0     = blockIdx.y * CTA_N;

    const uint32_t sb = smem_u32(sm);
    const uint32_t lmo = ((lane & 7) + ((lane >> 3) & 1) * 8) * RS + (lane >> 4) * 16;
    const uint32_t b_base = sb + S_B + (uint32_t)(warp_n * SPAN) * RS + lmo;
    const uint32_t a_off  = (uint32_t)(warp_m * 32) * RS + lmo;

    float acc[2][NI][4];
    #pragma unroll
    for (int mi = 0; mi < 2; mi++)
        #pragma unroll
        for (int ni = 0; ni < NI; ni++)
            #pragma unroll
            for (int c = 0; c < 4; c++) acc[mi][ni][c] = 0.f;

    auto load_b = [&](int kc) {
        #pragma unroll
        for (int i = 0; i < CTA_N / 32; i++) {
            const int slot = tid + i * 256;
            const int n    = slot >> 3;
            const int grp  = slot & 7;
            const size_t go = (size_t)(n0 + n) * K + kc * 64 + grp * 8;
            const uint4 vh = *reinterpret_cast<const uint4*>(Bh + go);
            const uint4 vl = *reinterpret_cast<const uint4*>(Bl + go);
            const int off = n * RS + grp * 16;
            *reinterpret_cast<uint4*>(sm + S_B + off) = vh;
            *reinterpret_cast<uint4*>(sm + S_B + CTA_N * RS + off) = vl;
        }
    };

    auto do_mma = [&](uint32_t abase) {
        #pragma unroll
        for (int s = 0; s < 3; s++) {
            const uint32_t ab = abase + ((s == 2) ? (uint32_t)AT : 0u);
            const uint32_t bb = b_base + ((s == 1) ? (uint32_t)(CTA_N * RS) : 0u);
            #pragma unroll
            for (int ks = 0; ks < 4; ks++) {
                uint32_t a[2][4];
                ldm4(a[0][0], a[0][1], a[0][2], a[0][3], ab + ks * 32);
                ldm4(a[1][0], a[1][1], a[1][2], a[1][3], ab + 16 * RS + ks * 32);
                uint32_t b[NI][2];
                #pragma unroll
                for (int p = 0; p < NI / 2; p++) {
                    uint32_t r0, r1, r2, r3;
                    ldm4(r0, r1, r2, r3, bb + (uint32_t)(p * 16) * RS + ks * 32);
                    b[2 * p][0] = r0; b[2 * p + 1][0] = r1;
                    b[2 * p][1] = r2; b[2 * p + 1][1] = r3;
                }
                #pragma unroll
                for (int mi = 0; mi < 2; mi++)
                    #pragma unroll
                    for (int ni = 0; ni < NI; ni++)
                        mma16816(acc[mi][ni], a[mi], b[ni]);
            }
        }
    };

    auto cp_a = [&](int kc, int buf) {
        #pragma unroll
        for (int i = 0; i < 4; i++) {
            const int slot = tid + i * 256;
            const int row  = slot >> 3;
            const int grp  = slot & 7;
            const int gm   = m0 + row;
            const bool ok  = (gm < M);
            const size_t go = (size_t)(ok ? gm : m0) * K + kc * 64 + grp * 8;
            const uint32_t dh = sb + (uint32_t)(buf * 2 * AT) + (uint32_t)(row * RS + grp * 16);
            const int ssz = ok ? 16 : 0;
            asm volatile("cp.async.cg.shared.global [%0], [%1], 16, %2;"
                         :: "r"(dh), "l"(Ah + go), "r"(ssz) : "memory");
            asm volatile("cp.async.cg.shared.global [%0], [%1], 16, %2;"
                         :: "r"(dh + AT), "l"(Al + go), "r"(ssz) : "memory");
        }
        asm volatile("cp.async.commit_group;" ::: "memory");
    };

    const int NC = K >> 6;
    int buf = 0;
    cp_a(0, 0);
    for (int kc = 0; kc < NC; kc++) {
        if (kc + 1 < NC) cp_a(kc + 1, buf ^ 1);
        load_b(kc);
        if (kc + 1 < NC) asm volatile("cp.async.wait_group 1;" ::: "memory");
        else             asm volatile("cp.async.wait_group 0;" ::: "memory");
        __syncthreads();
        do_mma(sb + (uint32_t)(buf * 2 * AT) + a_off);
        __syncthreads();
        buf ^= 1;
    }

    // ---- epilogue ----
    const int g = lane >> 2;
    const int t = lane & 3;
    #pragma unroll
    for (int mi = 0; mi < 2; mi++) {
        const int gm = m0 + warp_m * 32 + mi * 16 + g;
        int s0 = 0, s1 = 0, d0 = 0, d1 = 0;
        float c0 = 0.f, c1 = 0.f;
        if (MSG_OUT) {
            if (gm < M)     { s0 = src[gm];     c0 = cosv[gm]; }
            if (gm + 8 < M) { s1 = src[gm + 8]; c1 = cosv[gm + 8]; }
        }
        if (SCATTER_OUT) {
            if (gm < M)     d0 = dst[gm];
            if (gm + 8 < M) d1 = dst[gm + 8];
        }
        #pragma unroll
        for (int ni = 0; ni < NI; ni++) {
            const int gn = n0 + warp_n * SPAN + ni * 8 + t * 2;
            const float2 bb = *reinterpret_cast<const float2*>(bias + gn);
            #pragma unroll
            for (int half = 0; half < 2; half++) {
                const int gmr = gm + half * 8;
                if (gmr >= M) continue;
                float2 o = make_float2(acc[mi][ni][2 * half + 0] + bb.x,
                                       acc[mi][ni][2 * half + 1] + bb.y);
                if (RELU_OUT) { o.x = fmaxf(o.x, 0.f); o.y = fmaxf(o.y, 0.f); }
                if (MSG_OUT) {
                    const int   sr = half ? s1 : s0;
                    const float cr = half ? c1 : c0;
                    const float2 hv = *reinterpret_cast<const float2*>(hfeat + (size_t)sr * N + gn);
                    o.x = cr * o.x * hv.x; o.y = cr * o.y * hv.y;
                }
                if (SCATTER_OUT) {
                    const int dr = half ? d1 : d0;
                    asm volatile("red.global.add.v2.f32 [%0], {%1, %2};"
                                 :: "l"(C + (size_t)dr * N + gn), "f"(o.x), "f"(o.y) : "memory");
                } else if (OUT_SPLIT) {
                    const uint32_t hp = pack_bf16x2(o.x, o.y);
                    const float hx = __uint_as_float(hp << 16);
                    const float hy = __uint_as_float(hp & 0xFFFF0000u);
                    const uint32_t lp = pack_bf16x2(o.x - hx, o.y - hy);
                    *reinterpret_cast<uint32_t*>(Ch + (size_t)gmr * N + gn) = hp;
                    *reinterpret_cast<uint32_t*>(Cl + (size_t)gmr * N + gn) = lp;
                } else {
                    *reinterpret_cast<float2*>(C + (size_t)gmr * N + gn) = o;
                }
            }
        }
    }
}

// ---------------------------------------------------------------------------
// Chained layer-1 kernel: hN[dst] += relu( relu(m1@B1+b1) @ B2 + b2 )
// ---------------------------------------------------------------------------
__launch_bounds__(256, 2)
__global__ void gemm_chain(const __nv_bfloat16* __restrict__ Ah,
                           const __nv_bfloat16* __restrict__ Al,
                           const __nv_bfloat16* __restrict__ B1h,
                           const __nv_bfloat16* __restrict__ B1l,
                           const float* __restrict__ b1,
                           const __nv_bfloat16* __restrict__ B2h,
                           const __nv_bfloat16* __restrict__ B2l,
                           const float* __restrict__ b2,
                           float* __restrict__ hN,
                           const int* __restrict__ dst,
                           int M)
{
    extern __shared__ char sm[];
    constexpr int K = 128, N = 128;
    constexpr int S_B = 4 * AT;
    constexpr int NI  = 8;

    const int tid    = threadIdx.x;
    const int lane   = tid & 31;
    const int warp   = tid >> 5;
    const int warp_m = warp & 3;
    const int warp_n = warp >> 2;
    const int m0     = blockIdx.x * 128;

    const uint32_t sb = smem_u32(sm);
    const uint32_t lmo = ((lane & 7) + ((lane >> 3) & 1) * 8) * RS + (lane >> 4) * 16;
    const uint32_t b_base = sb + S_B + (uint32_t)(warp_n * 64) * RS + lmo;
    const uint32_t a_off  = (uint32_t)(warp_m * 32) * RS + lmo;

    float acc[2][NI][4];
    auto zero_acc = [&]() {
        #pragma unroll
        for (int mi = 0; mi < 2; mi++)
            #pragma unroll
            for (int ni = 0; ni < NI; ni++)
                #pragma unroll
                for (int c = 0; c < 4; c++) acc[mi][ni][c] = 0.f;
    };
    zero_acc();

    auto load_b = [&](const __nv_bfloat16* Bh, const __nv_bfloat16* Bl, int kc) {
        #pragma unroll
        for (int i = 0; i < 4; i++) {
            const int slot = tid + i * 256;
            const int n    = slot >> 3;
            const int grp  = slot & 7;
            const size_t go = (size_t)n * K + kc * 64 + grp * 8;
            const uint4 vh = *reinterpret_cast<const uint4*>(Bh + go);
            const uint4 vl = *reinterpret_cast<const uint4*>(Bl + go);
            const int off = n * RS + grp * 16;
            *reinterpret_cast<uint4*>(sm + S_B + off) = vh;
            *reinterpret_cast<uint4*>(sm + S_B + 128 * RS + off) = vl;
        }
    };

    auto do_mma = [&](uint32_t abase) {
        #pragma unroll
        for (int s = 0; s < 3; s++) {
            const uint32_t ab = abase + ((s == 2) ? (uint32_t)AT : 0u);
            const uint32_t bb = b_base + ((s == 1) ? (uint32_t)(128 * RS) : 0u);
            #pragma unroll
            for (int ks = 0; ks < 4; ks++) {
                uint32_t a[2][4];
                ldm4(a[0][0], a[0][1], a[0][2], a[0][3], ab + ks * 32);
                ldm4(a[1][0], a[1][1], a[1][2], a[1][3], ab + 16 * RS + ks * 32);
                uint32_t b[NI][2];
                #pragma unroll
                for (int p = 0; p < NI / 2; p++) {
                    uint32_t r0, r1, r2, r3;
                    ldm4(r0, r1, r2, r3, bb + (uint32_t)(p * 16) * RS + ks * 32);
                    b[2 * p][0] = r0; b[2 * p + 1][0] = r1;
                    b[2 * p][1] = r2; b[2 * p + 1][1] = r3;
                }
                #pragma unroll
                for (int mi = 0; mi < 2; mi++)
                    #pragma unroll
                    for (int ni = 0; ni < NI; ni++)
                        mma16816(acc[mi][ni], a[mi], b[ni]);
            }
        }
    };

    auto cp_a = [&](int kc, int buf) {
        #pragma unroll
        for (int i = 0; i < 4; i++) {
            const int slot = tid + i * 256;
            const int row  = slot >> 3;
            const int grp  = slot & 7;
            const int gm   = m0 + row;
            const bool ok  = (gm < M);
            const size_t go = (size_t)(ok ? gm : m0) * K + kc * 64 + grp * 8;
            const uint32_t dh = sb + (uint32_t)(buf * 2 * AT) + (uint32_t)(row * RS + grp * 16);
            const int ssz = ok ? 16 : 0;
            asm volatile("cp.async.cg.shared.global [%0], [%1], 16, %2;"
                         :: "r"(dh), "l"(Ah + go), "r"(ssz) : "memory");
            asm volatile("cp.async.cg.shared.global [%0], [%1], 16, %2;"
                         :: "r"(dh + AT), "l"(Al + go), "r"(ssz) : "memory");
        }
        asm volatile("cp.async.commit_group;" ::: "memory");
    };

    // ================= GEMM1: r1 = relu(m1 @ B1 + b1) =================
    cp_a(0, 0);
    cp_a(1, 1);
    for (int kc = 0; kc < 2; kc++) {
        load_b(B1h, B1l, kc);
        if (kc == 0) asm volatile("cp.async.wait_group 1;" ::: "memory");
        else         asm volatile("cp.async.wait_group 0;" ::: "memory");
        __syncthreads();
        do_mma(sb + (uint32_t)(kc * 2 * AT) + a_off);
        __syncthreads();
    }

    // ---- mid-epilogue: split r1 into SMEM A buffers (buf = warp_n) ----
    const int g = lane >> 2;
    const int t = lane & 3;
    {
        char* abuf = sm + warp_n * 2 * AT;
        #pragma unroll
        for (int mi = 0; mi < 2; mi++) {
            #pragma unroll
            for (int ni = 0; ni < NI; ni++) {
                const int col = ni * 8 + t * 2;
                const float2 bb = *reinterpret_cast<const float2*>(b1 + warp_n * 64 + col);
                #pragma unroll
                for (int half = 0; half < 2; half++) {
                    const int row = warp_m * 32 + mi * 16 + g + half * 8;
                    float ox = fmaxf(acc[mi][ni][2 * half + 0] + bb.x, 0.f);
                    float oy = fmaxf(acc[mi][ni][2 * half + 1] + bb.y, 0.f);
                    const uint32_t hp = pack_bf16x2(ox, oy);
                    const float hx = __uint_as_float(hp << 16);
                    const float hy = __uint_as_float(hp & 0xFFFF0000u);
                    const uint32_t lp = pack_bf16x2(ox - hx, oy - hy);
                    const int off = row * RS + col * 2;
                    *reinterpret_cast<uint32_t*>(abuf + off) = hp;
                    *reinterpret_cast<uint32_t*>(abuf + AT + off) = lp;
                }
            }
        }
    }
    zero_acc();
    __syncthreads();

    // ================= GEMM2: relu(r1 @ B2 + b2) -> scatter =================
    for (int kc = 0; kc < 2; kc++) {
        load_b(B2h, B2l, kc);
        __syncthreads();
        do_mma(sb + (uint32_t)(kc * 2 * AT) + a_off);
        __syncthreads();
    }

    #pragma unroll
    for (int mi = 0; mi < 2; mi++) {
        const int gm = m0 + warp_m * 32 + mi * 16 + g;
        int d0 = 0, d1 = 0;
        if (gm < M)     d0 = dst[gm];
        if (gm + 8 < M) d1 = dst[gm + 8];
        #pragma unroll
        for (int ni = 0; ni < NI; ni++) {
            const int gn = warp_n * 64 + ni * 8 + t * 2;
            const float2 bb = *reinterpret_cast<const float2*>(b2 + gn);
            #pragma unroll
            for (int half = 0; half < 2; half++) {
                const int gmr = gm + half * 8;
                if (gmr >= M) continue;
                float2 o = make_float2(fmaxf(acc[mi][ni][2 * half + 0] + bb.x, 0.f),
                                       fmaxf(acc[mi][ni][2 * half + 1] + bb.y, 0.f));
                const int dr = half ? d1 : d0;
                asm volatile("red.global.add.v2.f32 [%0], {%1, %2};"
                             :: "l"(hN + (size_t)dr * N + gn), "f"(o.x), "f"(o.y) : "memory");
            }
        }
    }
}

// ---------------------------------------------------------------------------
// Node GEMM with fused concat A
// ---------------------------------------------------------------------------
template<int CTA_N, bool RELU_OUT>
__launch_bounds__(256, 2)
__global__ void gemm_cat(const float* __restrict__ A1, int K1,
                         const float* __restrict__ A2,
                         const int* __restrict__ deg,
                         const __nv_bfloat16* __restrict__ Bh,
                         const __nv_bfloat16* __restrict__ Bl,
                         const float* __restrict__ bias,
                         float* __restrict__ C,
                         int M, int K, int N)
{
    extern __shared__ char sm[];
    constexpr int S_B  = 2 * AT;
    constexpr int SPAN = CTA_N / 2;
    constexpr int NI   = SPAN / 8;

    const int tid    = threadIdx.x;
    const int lane   = tid & 31;
    const int warp   = tid >> 5;
    const int warp_m = warp & 3;
    const int warp_n = warp >> 2;
    const int m0     = blockIdx.x * 128;
    const int n0     = blockIdx.y * CTA_N;
    const int K2     = K - K1;

    const uint32_t sb = smem_u32(sm);
    const uint32_t lmo = ((lane & 7) + ((lane >> 3) & 1) * 8) * RS + (lane >> 4) * 16;
    const uint32_t b_base = sb + S_B + (uint32_t)(warp_n * SPAN) * RS + lmo;
    const uint32_t a_base = sb + (uint32_t)(warp_m * 32) * RS + lmo;

    float acc[2][NI][4];
    #pragma unroll
    for (int mi = 0; mi < 2; mi++)
        #pragma unroll
        for (int ni = 0; ni < NI; ni++)
            #pragma unroll
            for (int c = 0; c < 4; c++) acc[mi][ni][c] = 0.f;

    const int NC = K >> 6;
    for (int kc = 0; kc < NC; kc++) {
        const bool second = (kc * 64 >= K1);
        #pragma unroll
        for (int i = 0; i < 8; i++) {
            const int slot = tid + i * 256;
            const int row  = slot >> 4;
            const int c4   = slot & 15;
            const int gm   = m0 + row;
            float4 v = make_float4(0.f, 0.f, 0.f, 0.f);
            if (gm < M) {
                if (!second) {
                    v = *reinterpret_cast<const float4*>(A1 + (size_t)gm * K1 + kc * 64 + c4 * 4);
                } else {
                    v = *reinterpret_cast<const float4*>(A2 + (size_t)gm * K2 + (kc * 64 - K1) + c4 * 4);
                    const float dv = fmaxf((float)deg[gm], 1.f);
                    v.x /= dv; v.y /= dv; v.z /= dv; v.w /= dv;
                }
            }
            uint32_t l0, l1;
            const uint32_t h0 = split2(v.x, v.y, l0);
            const uint32_t h1 = split2(v.z, v.w, l1);
            const int off = row * RS + c4 * 8;
            *reinterpret_cast<uint2*>(sm + off) = make_uint2(h0, h1);
            *reinterpret_cast<uint2*>(sm + AT + off) = make_uint2(l0, l1);
        }
        #pragma unroll
        for (int i = 0; i < CTA_N / 32; i++) {
            const int slot = tid + i * 256;
            const int n    = slot >> 3;
            const int grp  = slot & 7;
            const size_t go = (size_t)(n0 + n) * K + kc * 64 + grp * 8;
            const uint4 vh = *reinterpret_cast<const uint4*>(Bh + go);
            const uint4 vl = *reinterpret_cast<const uint4*>(Bl + go);
            const int off = n * RS + grp * 16;
            *reinterpret_cast<uint4*>(sm + S_B + off) = vh;
            *reinterpret_cast<uint4*>(sm + S_B + CTA_N * RS + off) = vl;
        }
        __syncthreads();

        #pragma unroll
        for (int s = 0; s < 3; s++) {
            const uint32_t ab = a_base + ((s == 2) ? (uint32_t)AT : 0u);
            const uint32_t bb = b_base + ((s == 1) ? (uint32_t)(CTA_N * RS) : 0u);
            #pragma unroll
            for (int ks = 0; ks < 4; ks++) {
                uint32_t a[2][4];
                ldm4(a[0][0], a[0][1], a[0][2], a[0][3], ab + ks * 32);
                ldm4(a[1][0], a[1][1], a[1][2], a[1][3], ab + 16 * RS + ks * 32);
                uint32_t b[NI][2];
                #pragma unroll
                for (int p = 0; p < NI / 2; p++) {
                    uint32_t r0, r1, r2, r3;
                    ldm4(r0, r1, r2, r3, bb + (uint32_t)(p * 16) * RS + ks * 32);
                    b[2 * p][0] = r0; b[2 * p + 1][0] = r1;
                    b[2 * p][1] = r2; b[2 * p + 1][1] = r3;
                }
                #pragma unroll
                for (int mi = 0; mi < 2; mi++)
                    #pragma unroll
                    for (int ni = 0; ni < NI; ni++)
                        mma16816(acc[mi][ni], a[mi], b[ni]);
            }
        }
        __syncthreads();
    }

    const int g = lane >> 2;
    const int t = lane & 3;
    #pragma unroll
    for (int mi = 0; mi < 2; mi++) {
        const int gm = m0 + warp_m * 32 + mi * 16 + g;
        #pragma unroll
        for (int ni = 0; ni < NI; ni++) {
            const int gn = n0 + warp_n * SPAN + ni * 8 + t * 2;
            const float2 bb = *reinterpret_cast<const float2*>(bias + gn);
            #pragma unroll
            for (int half = 0; half < 2; half++) {
                const int gmr = gm + half * 8;
                if (gmr >= M) continue;
                float2 o = make_float2(acc[mi][ni][2 * half + 0] + bb.x,
                                       acc[mi][ni][2 * half + 1] + bb.y);
                if (RELU_OUT) { o.x = fmaxf(o.x, 0.f); o.y = fmaxf(o.y, 0.f); }
                *reinterpret_cast<float2*>(C + (size_t)gmr * N + gn) = o;
            }
        }
    }
}

// ---------------------------------------------------------------------------
// fused norm+cosine: cos[e] = (hs.hd) / (max(|hs|,eps)*max(|hd|,eps))
// 4 edges per warp (8 lanes each); hs/hd loaded once, 3 dots accumulated.
// ---------------------------------------------------------------------------
template<int F>
__global__ void cosfull_kernel(const float* __restrict__ h,
                               const int* __restrict__ src,
                               const int* __restrict__ dst,
                               float* __restrict__ cosv)
{
    const int e  = blockIdx.x * 32 + (threadIdx.x >> 3);
    const int l8 = threadIdx.x & 7;
    const int s = src[e];
    const int d = dst[e];
    const float4* hs4 = reinterpret_cast<const float4*>(h + (size_t)s * F);
    const float4* hd4 = reinterpret_cast<const float4*>(h + (size_t)d * F);
    float ab = 0.f, aa = 0.f, bb = 0.f;
    #pragma unroll
    for (int p = 0; p < F / 32; p++) {
        const float4 a = hs4[l8 + p * 8];
        const float4 b = hd4[l8 + p * 8];
        ab += a.x * b.x + a.y * b.y + a.z * b.z + a.w * b.w;
        aa += a.x * a.x + a.y * a.y + a.z * a.z + a.w * a.w;
        bb += b.x * b.x + b.y * b.y + b.z * b.z + b.w * b.w;
    }
    #pragma unroll
    for (int o = 4; o > 0; o >>= 1) {
        ab += __shfl_xor_sync(0xFFFFFFFFu, ab, o);
        aa += __shfl_xor_sync(0xFFFFFFFFu, aa, o);
        bb += __shfl_xor_sync(0xFFFFFFFFu, bb, o);
    }
    if (l8 == 0) {
        const float ia = 1.f / fmaxf(sqrtf(aa), 1e-12f);
        const float ib = 1.f / fmaxf(sqrtf(bb), 1e-12f);
        cosv[e] = ab * ia * ib;
    }
}

// ---------------------------------------------------------------------------
// w1+msg1 fused, emitting pre-split bf16
// ---------------------------------------------------------------------------
__global__ void w1msg_kernel(const float* __restrict__ ef, const float* __restrict__ We,
                             const float* __restrict__ be,
                             const int* __restrict__ src,
                             const float* __restrict__ cosv,
                             const float* __restrict__ nf,
                             __nv_bfloat16* __restrict__ m1h, __nv_bfloat16* __restrict__ m1l,
                             __nv_bfloat16* __restrict__ rwh, __nv_bfloat16* __restrict__ rwl)
{
    const int idx = blockIdx.x * 256 + threadIdx.x;
    const int e = idx >> 7;
    const int j = idx & 127;
    const float e0 = ef[2 * e];
    const float e1 = ef[2 * e + 1];
    const float w = fmaf(e1, We[128 + j], fmaf(e0, We[j], be[j]));
    const float m = cosv[e] * w * nf[(size_t)src[e] * 128 + j];
    const float rw = fmaxf(w, 0.f);
    const __nv_bfloat16 mh = __float2bfloat16(m);
    m1h[idx] = mh;
    m1l[idx] = __float2bfloat16(m - __bfloat162float(mh));
    const __nv_bfloat16 rh = __float2bfloat16(rw);
    rwh[idx] = rh;
    rwl[idx] = __float2bfloat16(rw - __bfloat162float(rh));
}

// ---------------------------------------------------------------------------
// degree
// ---------------------------------------------------------------------------
__global__ void deg_kernel(const int* __restrict__ dst, int* __restrict__ deg)
{
    const int e = blockIdx.x * 256 + threadIdx.x;
    if (e < NE) atomicAdd(&deg[dst[e]], 1);
}

// ---------------------------------------------------------------------------
// launch  (kernel #6 == gemm_chain, so ncu -s 5 -c 1 profiles the edge GEMM)
// ---------------------------------------------------------------------------
extern "C" void kernel_launch(void* const* d_in, const int* in_sizes, int n_in,
                              void* d_out, int out_size)
{
    (void)in_sizes; (void)n_in; (void)out_size;

    const float* nf   = (const float*)d_in[0];
    const float* ef   = (const float*)d_in[1];
    const int*   src  = (const int*)  d_in[2];
    const int*   dst  = (const int*)  d_in[3];
    const float* We1  = (const float*)d_in[4];
    const float* be1  = (const float*)d_in[5];
    const float* Wr1a = (const float*)d_in[6];
    const float* br1a = (const float*)d_in[7];
    const float* Wr1b = (const float*)d_in[8];
    const float* br1b = (const float*)d_in[9];
    const float* Wl1  = (const float*)d_in[10];
    const float* bl1  = (const float*)d_in[11];
    const float* We2  = (const float*)d_in[12];
    const float* be2  = (const float*)d_in[13];
    const float* Wr2a = (const float*)d_in[14];
    const float* br2a = (const float*)d_in[15];
    const float* Wr2b = (const float*)d_in[16];
    const float* br2b = (const float*)d_in[17];
    const float* Wl2  = (const float*)d_in[18];
    const float* bl2  = (const float*)d_in[19];
    float* out = (float*)d_out;

    float *p_h1, *p_hN, *p_cos;
    int*   p_deg;
    __nv_bfloat16 *p_bwh, *p_bwl, *p_p1h, *p_p1l, *p_p2h, *p_p2l, *p_rwh, *p_rwl;
    cudaGetSymbolAddress((void**)&p_h1,  g_h1);
    cudaGetSymbolAddress((void**)&p_hN,  g_hN);
    cudaGetSymbolAddress((void**)&p_cos, g_cos);
    cudaGetSymbolAddress((void**)&p_deg, g_deg);
    cudaGetSymbolAddress((void**)&p_bwh, g_bwh);
    cudaGetSymbolAddress((void**)&p_bwl, g_bwl);
    cudaGetSymbolAddress((void**)&p_p1h, g_p1h);
    cudaGetSymbolAddress((void**)&p_p1l, g_p1l);
    cudaGetSymbolAddress((void**)&p_p2h, g_p2h);
    cudaGetSymbolAddress((void**)&p_p2l, g_p2l);
    cudaGetSymbolAddress((void**)&p_rwh, g_rwh);
    cudaGetSymbolAddress((void**)&p_rwl, g_rwl);

    constexpr int SM_BF128 = 4 * 18432 + 2 * 128 * 144;   // 110592
    constexpr int SM_CT128 = 2 * 18432 + 2 * 128 * 144;   // 73728
    constexpr int SM_CT32  = 2 * 18432 + 2 * 32  * 144;   // 46080

    auto Gsplit = gemm_mma<128, true,  false, false, true >;
    auto Gscat  = gemm_mma<128, true,  false, true,  false>;
    auto Gmsg   = gemm_mma<128, false, true,  false, true >;
    auto Gcat1  = gemm_cat<128, true >;
    auto Gcat2  = gemm_cat<32,  false>;
    cudaFuncSetAttribute(Gsplit, cudaFuncAttributeMaxDynamicSharedMemorySize, SM_BF128);
    cudaFuncSetAttribute(Gscat,  cudaFuncAttributeMaxDynamicSharedMemorySize, SM_BF128);
    cudaFuncSetAttribute(Gmsg,   cudaFuncAttributeMaxDynamicSharedMemorySize, SM_BF128);
    cudaFuncSetAttribute(gemm_chain, cudaFuncAttributeMaxDynamicSharedMemorySize, SM_BF128);
    cudaFuncSetAttribute(Gcat1,  cudaFuncAttributeMaxDynamicSharedMemorySize, SM_CT128);
    cudaFuncSetAttribute(Gcat2,  cudaFuncAttributeMaxDynamicSharedMemorySize, SM_CT32);

    const int EG = NE / 128;              // 6250 edge M-tiles
    const int VG = (NN + 127) / 128;      // 391 node M-tiles

    // ---- kernels 1..5: chain prerequisites ----
    zero_kernel<<<(NN * F1 / 4 + 255) / 256, 256>>>(
        reinterpret_cast<float4*>(p_hN), NN * F1 / 4);                      // 1
    conv_w_kernel<<<(128 * 128 + 255) / 256, 256>>>(Wr1a, 128, 128,
                                                    p_bwh + 0, p_bwl + 0); // 2
    conv_w_kernel<<<(128 * 128 + 255) / 256, 256>>>(Wr1b, 128, 128,
                                                    p_bwh + 16384, p_bwl + 16384); // 3
    cosfull_kernel<F1><<<NE / 32, 256>>>(nf, src, dst, p_cos);              // 4
    w1msg_kernel<<<(NE * F1) / 256, 256>>>(ef, We1, be1, src, p_cos, nf,
                                           p_p1h, p_p1l, p_rwh, p_rwl);     // 5

    // kernel 6 (ncu target): chained layer-1 edge GEMMs + scatter
    gemm_chain<<<EG, 256, SM_BF128>>>(
        p_p1h, p_p1l, p_bwh + 0, p_bwl + 0, br1a,
        p_bwh + 16384, p_bwl + 16384, br1b, p_hN, dst, NE);

    // ---- deg + remaining weight pre-splits (needed before node GEMMs) ----
    cudaMemsetAsync(p_deg, 0, NN * sizeof(int));
    deg_kernel<<<(NE + 255) / 256, 256>>>(dst, p_deg);
    conv_w_kernel<<<(128 * 256 + 255) / 256, 256>>>(We2,  128, 256, p_bwh + 32768,  p_bwl + 32768);
    conv_w_kernel<<<(256 * 256 + 255) / 256, 256>>>(Wr2a, 256, 256, p_bwh + 65536,  p_bwl + 65536);
    conv_w_kernel<<<(256 * 256 + 255) / 256, 256>>>(Wr2b, 256, 256, p_bwh + 131072, p_bwl + 131072);
    conv_w_kernel<<<(256 * 256 + 255) / 256, 256>>>(Wl1,  256, 256, p_bwh + 196608, p_bwl + 196608);
    conv_w_kernel<<<(512 * 32  + 255) / 256, 256>>>(Wl2,  512, 32,  p_bwh + 262144, p_bwl + 262144);

    // Gl1 (fused concat): h1 = relu([nf | hN/deg] @ Wl1 + bl1)
    Gcat1<<<dim3(VG, 2), 256, SM_CT128>>>(
        nf, 128, p_hN, p_deg, p_bwh + 196608, p_bwl + 196608, bl1,
        p_h1, NN, 256, 256);

    // ======================= layer 2 =======================
    cosfull_kernel<HF><<<NE / 32, 256>>>(p_h1, src, dst, p_cos);
    cudaMemsetAsync(p_hN, 0, (size_t)NN * HF * sizeof(float));

    // Ge2: m2 = cos * (relu(w1) @ We2 + be2) * h1[src] -> split into p2
    Gmsg<<<dim3(EG, 2), 256, SM_BF128>>>(
        p_rwh, p_rwl, p_bwh + 32768, p_bwl + 32768, be2,
        nullptr, p_p2h, p_p2l, NE, 128, 256, p_cos, p_h1, src, nullptr);

    // G2a: r2 = relu(m2 @ Wr2a + br2a) -> split into p1
    Gsplit<<<dim3(EG, 2), 256, SM_BF128>>>(
        p_p2h, p_p2l, p_bwh + 65536, p_bwl + 65536, br2a,
        nullptr, p_p1h, p_p1l, NE, 256, 256, nullptr, nullptr, nullptr, nullptr);

    // G2b: hN[dst] += relu(r2 @ Wr2b + br2b)
    Gscat<<<dim3(EG, 2), 256, SM_BF128>>>(
        p_p1h, p_p1l, p_bwh + 131072, p_bwl + 131072, br2b,
        p_hN, nullptr, nullptr, NE, 256, 256, nullptr, nullptr, nullptr, dst);

    // Gl2 (fused concat): out = [h1 | hN/deg] @ Wl2 + bl2
    Gcat2<<<dim3(VG, 1), 256, SM_CT32>>>(
        p_h1, 256, p_hN, p_deg, p_bwh + 262144, p_bwl + 262144, bl2,
        out, NN, 512, 32);
}